// round 7
// baseline (speedup 1.0000x reference)
#include <cuda_runtime.h>
#include <cuda_fp16.h>
#include <cstdint>

#define NN 100000
#define NE 1600000
#define C  64
#define NBLK 98           // ceil(100000/1024)

// ---- device scratch (no allocation allowed) ----
__device__ int    g_deg[NN];
__device__ int    g_off[NN];
__device__ int    g_cur[NN];
__device__ float  g_dinv[NN];
__device__ int    g_srcs[NE];
__device__ float  g_h1[(size_t)NN * C];
__device__ float  g_h2[(size_t)NN * C];
__device__ float  g_agg[(size_t)NN * C];
__device__ __half g_hf[(size_t)NN * C];     // fp16 shadow of current layer input (gather table)
__device__ float  g_Whi[3][2][C * C];       // [layer][0=Wl,1=Wr] transposed k-major, tf32-hi
__device__ float  g_Wlo[3][2][C * C];       // tf32-lo part
__device__ int    g_bsum[128];
__device__ int    g_boff[128];

// ---------------- helpers ----------------
__device__ __forceinline__ uint32_t f2tf(float v) {
    uint32_t r;
    asm("cvt.rna.tf32.f32 %0, %1;" : "=r"(r) : "f"(v));
    return r;
}

__device__ __forceinline__ void mma8(float* c, uint32_t a0, uint32_t a1, uint32_t a2, uint32_t a3,
                                     uint32_t b0, uint32_t b1) {
    asm volatile("mma.sync.aligned.m16n8k8.row.col.f32.tf32.tf32.f32 "
                 "{%0,%1,%2,%3}, {%4,%5,%6,%7}, {%8,%9}, {%0,%1,%2,%3};"
                 : "+f"(c[0]), "+f"(c[1]), "+f"(c[2]), "+f"(c[3])
                 : "r"(a0), "r"(a1), "r"(a2), "r"(a3), "r"(b0), "r"(b1));
}

// ---------------- CSR build ----------------
__global__ void zero_deg_k() {
    int i = blockIdx.x * blockDim.x + threadIdx.x;
    if (i < NN) g_deg[i] = 0;
}

// edge_index is int32 on device (JAX default x64-disabled downcasts int64).
__global__ void count_k(const int* __restrict__ ei) {
    int e = blockIdx.x * blockDim.x + threadIdx.x;
    if (e < NE) {
        int dst = ei[NE + e];
        if ((unsigned)dst < (unsigned)NN) atomicAdd(&g_deg[dst], 1);
    }
}

// two-level scan: block sums
__global__ void bsum_k() {
    __shared__ int ws[32];
    int t = threadIdx.x, b = blockIdx.x;
    int i = b * 1024 + t;
    int v = (i < NN) ? g_deg[i] : 0;
    #pragma unroll
    for (int o = 16; o > 0; o >>= 1) v += __shfl_down_sync(0xffffffffu, v, o);
    if ((t & 31) == 0) ws[t >> 5] = v;
    __syncthreads();
    if (t < 32) {
        int s = ws[t];
        #pragma unroll
        for (int o = 16; o > 0; o >>= 1) s += __shfl_down_sync(0xffffffffu, s, o);
        if (t == 0) g_bsum[b] = s;
    }
}

// scan the 98 block sums (1 block of 128)
__global__ void bscan_k() {
    __shared__ int ws[4];
    int t = threadIdx.x, lane = t & 31, w = t >> 5;
    int v = (t < NBLK) ? g_bsum[t] : 0;
    int x = v;
    #pragma unroll
    for (int o = 1; o < 32; o <<= 1) {
        int y = __shfl_up_sync(0xffffffffu, x, o);
        if (lane >= o) x += y;
    }
    if (lane == 31) ws[w] = x;
    __syncthreads();
    int pre = 0;
    if (w > 0) {
        #pragma unroll
        for (int j = 0; j < 3; j++) if (j < w) pre += ws[j];
    }
    if (t < NBLK) g_boff[t] = pre + x - v;   // exclusive
}

// per-tile rescan + add block offset; write off/cur/dinv
__global__ void scatter_scan_k() {
    __shared__ int wsum[32];
    int t = threadIdx.x, b = blockIdx.x;
    int lane = t & 31, w = t >> 5;
    int i = b * 1024 + t;
    int v = (i < NN) ? g_deg[i] : 0;
    int x = v;
    #pragma unroll
    for (int o = 1; o < 32; o <<= 1) {
        int y = __shfl_up_sync(0xffffffffu, x, o);
        if (lane >= o) x += y;
    }
    if (lane == 31) wsum[w] = x;
    __syncthreads();
    if (w == 0) {
        int s = wsum[lane];
        #pragma unroll
        for (int o = 1; o < 32; o <<= 1) {
            int y = __shfl_up_sync(0xffffffffu, s, o);
            if (lane >= o) s += y;
        }
        wsum[lane] = s;
    }
    __syncthreads();
    int pre = (w > 0) ? wsum[w - 1] : 0;
    if (i < NN) {
        int excl = g_boff[b] + pre + x - v;
        g_off[i]  = excl;
        g_cur[i]  = excl;
        g_dinv[i] = 1.0f / (float)((v > 0) ? v : 1);
    }
}

__global__ void fill_k(const int* __restrict__ ei) {
    int e = blockIdx.x * blockDim.x + threadIdx.x;
    if (e < NE) {
        int src = ei[e];
        int dst = ei[NE + e];
        if ((unsigned)dst < (unsigned)NN && (unsigned)src < (unsigned)NN) {
            int p = atomicAdd(&g_cur[dst], 1);
            if ((unsigned)p < (unsigned)NE) g_srcs[p] = src;
        }
    }
}

// ---------------- x -> fp16 shadow (once per launch) ----------------
__global__ void h2f_k(const float* __restrict__ x) {
    int i = blockIdx.x * blockDim.x + threadIdx.x;   // one float4 -> 2 half2
    const int total = NN * C / 4;
    if (i < total) {
        float4 v = ((const float4*)x)[i];
        __half2 lo = __floats2half2_rn(v.x, v.y);
        __half2 hi = __floats2half2_rn(v.z, v.w);
        uint2 p;
        p.x = *(uint32_t*)&lo;
        p.y = *(uint32_t*)&hi;
        ((uint2*)g_hf)[i] = p;
    }
}

// ---------------- weight transpose + tf32 hi/lo split (once, tiny) ----------------
__global__ void wtrans_k(const float* __restrict__ Wl0, const float* __restrict__ Wr0,
                         const float* __restrict__ Wl1, const float* __restrict__ Wr1,
                         const float* __restrict__ Wl2, const float* __restrict__ Wr2) {
    int l = blockIdx.x;  // 0..2
    const float* Wl = (l == 0) ? Wl0 : (l == 1) ? Wl1 : Wl2;
    const float* Wr = (l == 0) ? Wr0 : (l == 1) ? Wr1 : Wr2;
    for (int idx = threadIdx.x; idx < C * C; idx += blockDim.x) {
        int k = idx >> 6, c = idx & 63;
        float vl = Wl[c * C + k];
        float vr = Wr[c * C + k];
        uint32_t hl = f2tf(vl);
        uint32_t hr = f2tf(vr);
        float hlf = __uint_as_float(hl);
        float hrf = __uint_as_float(hr);
        g_Whi[l][0][idx] = hlf;
        g_Wlo[l][0][idx] = __uint_as_float(f2tf(vl - hlf));
        g_Whi[l][1][idx] = hrf;
        g_Wlo[l][1][idx] = __uint_as_float(f2tf(vr - hrf));
    }
}

// ---------------- mean aggregation: warp per node, fp16 gather ----------------
// 8-lane group per edge: lane loads uint4 = 8 halves (16B); 8 lanes cover the 128B row.
// Warp streams 4 edges per step. fp32 accumulation, cross-group shfl reduction.
__global__ void __launch_bounds__(256) agg_k() {
    int warp = (blockIdx.x * blockDim.x + threadIdx.x) >> 5;
    int lane = threadIdx.x & 31;
    if (warp >= NN) return;
    int grp = lane >> 3;      // 0..3: which edge of the quad
    int q   = lane & 7;       // 16B chunk within the row (channels q*8..q*8+7)
    int s = g_off[warp];
    int d = g_deg[warp];
    float a0 = 0.f, a1 = 0.f, a2 = 0.f, a3 = 0.f;
    float a4 = 0.f, a5 = 0.f, a6 = 0.f, a7 = 0.f;
    const uint4* hf = (const uint4*)g_hf;    // row = 8 uint4
    int i = 0;
    for (; i + 4 <= d; i += 4) {
        int u = g_srcs[s + i + grp];
        uint4 t = hf[(size_t)u * 8 + q];
        float2 f0 = __half22float2(*(__half2*)&t.x);
        float2 f1 = __half22float2(*(__half2*)&t.y);
        float2 f2 = __half22float2(*(__half2*)&t.z);
        float2 f3 = __half22float2(*(__half2*)&t.w);
        a0 += f0.x; a1 += f0.y; a2 += f1.x; a3 += f1.y;
        a4 += f2.x; a5 += f2.y; a6 += f3.x; a7 += f3.y;
    }
    int r = d - i;
    if (grp < r) {
        int u = g_srcs[s + i + grp];
        uint4 t = hf[(size_t)u * 8 + q];
        float2 f0 = __half22float2(*(__half2*)&t.x);
        float2 f1 = __half22float2(*(__half2*)&t.y);
        float2 f2 = __half22float2(*(__half2*)&t.z);
        float2 f3 = __half22float2(*(__half2*)&t.w);
        a0 += f0.x; a1 += f0.y; a2 += f1.x; a3 += f1.y;
        a4 += f2.x; a5 += f2.y; a6 += f3.x; a7 += f3.y;
    }
    // reduce across the 4 groups (lanes q, q+8, q+16, q+24)
    #pragma unroll
    for (int o = 16; o >= 8; o >>= 1) {
        a0 += __shfl_down_sync(0xffffffffu, a0, o);
        a1 += __shfl_down_sync(0xffffffffu, a1, o);
        a2 += __shfl_down_sync(0xffffffffu, a2, o);
        a3 += __shfl_down_sync(0xffffffffu, a3, o);
        a4 += __shfl_down_sync(0xffffffffu, a4, o);
        a5 += __shfl_down_sync(0xffffffffu, a5, o);
        a6 += __shfl_down_sync(0xffffffffu, a6, o);
        a7 += __shfl_down_sync(0xffffffffu, a7, o);
    }
    if (lane < 8) {
        float di = g_dinv[warp];
        float4 r0 = make_float4(a0 * di, a1 * di, a2 * di, a3 * di);
        float4 r1 = make_float4(a4 * di, a5 * di, a6 * di, a7 * di);
        float4* dst = (float4*)(g_agg + (size_t)warp * C + q * 8);
        dst[0] = r0;
        dst[1] = r1;
    }
}

// ---------------- tensor-core transform: 3xTF32 dual GEMM ----------------
// out[v][c] = sum_k agg[v][k]*WlT[k][c] + bl[c] + sum_k h[v][k]*WrT[k][c] (+relu)
// Block = 64 nodes x 64 channels, 256 threads (8 warps). Also writes fp16 shadow
// of the output (next layer's gather table) unless final layer.
#define WS 72
#define AS 68
__global__ void __launch_bounds__(256) xform_k(const float* __restrict__ x,
                                               const float* __restrict__ bl,
                                               float* __restrict__ outp,
                                               int layer, int insel, int outsel,
                                               int relu) {
    extern __shared__ float sm[];
    float* sWlHi = sm;                       // [64][WS]
    float* sWlLo = sWlHi + C * WS;
    float* sWrHi = sWlLo + C * WS;
    float* sWrLo = sWrHi + C * WS;
    float* sA    = sWrLo + C * WS;           // [64][AS]
    float* sH    = sA + 64 * AS;

    const float* hin = (insel == 0) ? x : (insel == 1) ? g_h1 : g_h2;
    float* outb = (outsel == 1) ? g_h1 : (outsel == 2) ? g_h2 : outp;

    int tid = threadIdx.x;
    int v0  = blockIdx.x * 64;

    // stage weights (coalesced reads; STS bank = 8k + c, conflict-free)
    const float* whl = g_Whi[layer][0];
    const float* wll = g_Wlo[layer][0];
    const float* whr = g_Whi[layer][1];
    const float* wlr = g_Wlo[layer][1];
    #pragma unroll
    for (int it = 0; it < 16; it++) {
        int i = it * 256 + tid;
        int k = i >> 6, c = i & 63;
        int p = k * WS + c;
        sWlHi[p] = whl[i];
        sWlLo[p] = wll[i];
        sWrHi[p] = whr[i];
        sWrLo[p] = wlr[i];
    }
    // stage A/H (64 rows x 16 float4)
    #pragma unroll
    for (int it = 0; it < 4; it++) {
        int i = it * 256 + tid;        // 0..1023
        int n = i >> 4, q = i & 15;
        int v = v0 + n;
        float4 a = make_float4(0.f, 0.f, 0.f, 0.f), h = a;
        if (v < NN) {
            a = ((const float4*)(g_agg + (size_t)v * C))[q];
            h = ((const float4*)(hin   + (size_t)v * C))[q];
        }
        int base = n * AS + q * 4;
        sA[base + 0] = a.x; sA[base + 1] = a.y; sA[base + 2] = a.z; sA[base + 3] = a.w;
        sH[base + 0] = h.x; sH[base + 1] = h.y; sH[base + 2] = h.z; sH[base + 3] = h.w;
    }
    __syncthreads();

    int lane = tid & 31, gid = lane >> 2, tig = lane & 3;
    int wid = tid >> 5, mg = wid >> 2, ng = wid & 3;

    // accumulators init with bias
    float acc[2][2][4];
    #pragma unroll
    for (int nt = 0; nt < 2; nt++) {
        int col = ng * 16 + nt * 8 + 2 * tig;
        float b0 = bl[col], b1 = bl[col + 1];
        #pragma unroll
        for (int mt = 0; mt < 2; mt++) {
            acc[mt][nt][0] = b0; acc[mt][nt][1] = b1;
            acc[mt][nt][2] = b0; acc[mt][nt][3] = b1;
        }
    }

    for (int ks = 0; ks < 8; ks++) {
        int k0 = ks * 8;
        uint32_t blh[2][2], bll[2][2], brh[2][2], brl[2][2];
        #pragma unroll
        for (int nt = 0; nt < 2; nt++) {
            int n = ng * 16 + nt * 8 + gid;
            int p0 = (k0 + tig) * WS + n;
            int p1 = (k0 + tig + 4) * WS + n;
            blh[nt][0] = __float_as_uint(sWlHi[p0]); blh[nt][1] = __float_as_uint(sWlHi[p1]);
            bll[nt][0] = __float_as_uint(sWlLo[p0]); bll[nt][1] = __float_as_uint(sWlLo[p1]);
            brh[nt][0] = __float_as_uint(sWrHi[p0]); brh[nt][1] = __float_as_uint(sWrHi[p1]);
            brl[nt][0] = __float_as_uint(sWrLo[p0]); brl[nt][1] = __float_as_uint(sWrLo[p1]);
        }
        #pragma unroll
        for (int mt = 0; mt < 2; mt++) {
            int r = mg * 32 + mt * 16 + gid;   // local row
            int pa = r * AS + k0 + tig;
            int pb = (r + 8) * AS + k0 + tig;
            float a0f = sA[pa], a1f = sA[pb], a2f = sA[pa + 4], a3f = sA[pb + 4];
            float h0f = sH[pa], h1f = sH[pb], h2f = sH[pa + 4], h3f = sH[pb + 4];
            uint32_t ah0 = f2tf(a0f), ah1 = f2tf(a1f), ah2 = f2tf(a2f), ah3 = f2tf(a3f);
            uint32_t al0 = f2tf(a0f - __uint_as_float(ah0));
            uint32_t al1 = f2tf(a1f - __uint_as_float(ah1));
            uint32_t al2 = f2tf(a2f - __uint_as_float(ah2));
            uint32_t al3 = f2tf(a3f - __uint_as_float(ah3));
            uint32_t hh0 = f2tf(h0f), hh1 = f2tf(h1f), hh2 = f2tf(h2f), hh3 = f2tf(h3f);
            uint32_t hl0 = f2tf(h0f - __uint_as_float(hh0));
            uint32_t hl1 = f2tf(h1f - __uint_as_float(hh1));
            uint32_t hl2 = f2tf(h2f - __uint_as_float(hh2));
            uint32_t hl3 = f2tf(h3f - __uint_as_float(hh3));
            #pragma unroll
            for (int nt = 0; nt < 2; nt++) {
                float* cc = acc[mt][nt];
                mma8(cc, ah0, ah1, ah2, ah3, blh[nt][0], blh[nt][1]);  // hi*hi
                mma8(cc, al0, al1, al2, al3, blh[nt][0], blh[nt][1]);  // lo*hi
                mma8(cc, ah0, ah1, ah2, ah3, bll[nt][0], bll[nt][1]);  // hi*lo
                mma8(cc, hh0, hh1, hh2, hh3, brh[nt][0], brh[nt][1]);
                mma8(cc, hl0, hl1, hl2, hl3, brh[nt][0], brh[nt][1]);
                mma8(cc, hh0, hh1, hh2, hh3, brl[nt][0], brl[nt][1]);
            }
        }
    }

    int writeHalf = (outsel != 0);   // final layer output is not gathered again
    #pragma unroll
    for (int mt = 0; mt < 2; mt++) {
        int row = v0 + mg * 32 + mt * 16 + gid;
        #pragma unroll
        for (int nt = 0; nt < 2; nt++) {
            int col = ng * 16 + nt * 8 + 2 * tig;
            float2 r0 = make_float2(acc[mt][nt][0], acc[mt][nt][1]);
            float2 r1 = make_float2(acc[mt][nt][2], acc[mt][nt][3]);
            if (relu) {
                r0.x = fmaxf(r0.x, 0.f); r0.y = fmaxf(r0.y, 0.f);
                r1.x = fmaxf(r1.x, 0.f); r1.y = fmaxf(r1.y, 0.f);
            }
            if (row < NN) {
                *(float2*)(outb + (size_t)row * C + col) = r0;
                if (writeHalf) {
                    __half2 p = __floats2half2_rn(r0.x, r0.y);
                    *(__half2*)((__half*)g_hf + (size_t)row * C + col) = p;
                }
            }
            if (row + 8 < NN) {
                *(float2*)(outb + (size_t)(row + 8) * C + col) = r1;
                if (writeHalf) {
                    __half2 p = __floats2half2_rn(r1.x, r1.y);
                    *(__half2*)((__half*)g_hf + (size_t)(row + 8) * C + col) = p;
                }
            }
        }
    }
}

extern "C" void kernel_launch(void* const* d_in, const int* in_sizes, int n_in,
                              void* d_out, int out_size) {
    const float* x   = (const float*)d_in[0];
    const int*   ei  = (const int*)d_in[1];    // int32 (JAX x64-disabled)
    const float* Wl0 = (const float*)d_in[2];
    const float* bl0 = (const float*)d_in[3];
    const float* Wr0 = (const float*)d_in[4];
    const float* Wl1 = (const float*)d_in[5];
    const float* bl1 = (const float*)d_in[6];
    const float* Wr1 = (const float*)d_in[7];
    const float* Wl2 = (const float*)d_in[8];
    const float* bl2 = (const float*)d_in[9];
    const float* Wr2 = (const float*)d_in[10];
    float* out = (float*)d_out;

    const int XSMEM = (4 * C * WS + 2 * 64 * AS) * (int)sizeof(float);  // 108544 B
    cudaFuncSetAttribute(xform_k, cudaFuncAttributeMaxDynamicSharedMemorySize, XSMEM);

    // CSR build + weight prep + fp16 shadow of x
    zero_deg_k<<<(NN + 255) / 256, 256>>>();
    count_k<<<(NE + 255) / 256, 256>>>(ei);
    bsum_k<<<NBLK, 1024>>>();
    bscan_k<<<1, 128>>>();
    scatter_scan_k<<<NBLK, 1024>>>();
    fill_k<<<(NE + 255) / 256, 256>>>(ei);
    wtrans_k<<<3, 256>>>(Wl0, Wr0, Wl1, Wr1, Wl2, Wr2);
    h2f_k<<<(NN * C / 4 + 255) / 256, 256>>>(x);

    const int AGG_BLOCKS = (NN + 7) / 8;     // 8 warps (nodes) per 256-thread block
    const int XF_BLOCKS  = (NN + 63) / 64;   // 64 nodes per block

    agg_k<<<AGG_BLOCKS, 256>>>();
    xform_k<<<XF_BLOCKS, 256, XSMEM>>>(x, bl0, out, 0, 0, 1, 1);  // x    -> g_h1 (+fp16)
    agg_k<<<AGG_BLOCKS, 256>>>();
    xform_k<<<XF_BLOCKS, 256, XSMEM>>>(x, bl1, out, 1, 1, 2, 1);  // g_h1 -> g_h2 (+fp16)
    agg_k<<<AGG_BLOCKS, 256>>>();
    xform_k<<<XF_BLOCKS, 256, XSMEM>>>(x, bl2, out, 2, 2, 0, 0);  // g_h2 -> out
}

// round 8
// speedup vs baseline: 1.0396x; 1.0396x over previous
#include <cuda_runtime.h>
#include <cstdint>

#define NN 100000
#define NE 1600000
#define C  64
#define NBLK 98           // ceil(100000/1024)

// ---- device scratch (no allocation allowed) ----
__device__ int   g_deg[NN];
__device__ int   g_off[NN];
__device__ int   g_cur[NN];
__device__ int   g_srcs[NE];
__device__ float g_h1[(size_t)NN * C];
__device__ float g_h2[(size_t)NN * C];
__device__ float g_agg[(size_t)NN * C];
__device__ float g_Whi[3][2][C * C];   // [layer][0=Wl,1=Wr] transposed k-major, tf32-hi
__device__ float g_Wlo[3][2][C * C];   // tf32-lo part
__device__ int   g_bsum[128];
__device__ int   g_boff[128];

// ---------------- helpers ----------------
__device__ __forceinline__ uint32_t f2tf(float v) {
    uint32_t r;
    asm("cvt.rna.tf32.f32 %0, %1;" : "=r"(r) : "f"(v));
    return r;
}

__device__ __forceinline__ void mma8(float* c, uint32_t a0, uint32_t a1, uint32_t a2, uint32_t a3,
                                     uint32_t b0, uint32_t b1) {
    asm volatile("mma.sync.aligned.m16n8k8.row.col.f32.tf32.tf32.f32 "
                 "{%0,%1,%2,%3}, {%4,%5,%6,%7}, {%8,%9}, {%0,%1,%2,%3};"
                 : "+f"(c[0]), "+f"(c[1]), "+f"(c[2]), "+f"(c[3])
                 : "r"(a0), "r"(a1), "r"(a2), "r"(a3), "r"(b0), "r"(b1));
}

// ---------------- CSR build ----------------
__global__ void zero_deg_k() {
    int i = blockIdx.x * blockDim.x + threadIdx.x;
    if (i < NN) g_deg[i] = 0;
}

// edge_index is int32 on device (JAX default x64-disabled downcasts int64).
__global__ void count_k(const int* __restrict__ ei) {
    int e = blockIdx.x * blockDim.x + threadIdx.x;
    if (e < NE) {
        int dst = ei[NE + e];
        if ((unsigned)dst < (unsigned)NN) atomicAdd(&g_deg[dst], 1);
    }
}

// two-level scan: block sums
__global__ void bsum_k() {
    __shared__ int ws[32];
    int t = threadIdx.x, b = blockIdx.x;
    int i = b * 1024 + t;
    int v = (i < NN) ? g_deg[i] : 0;
    #pragma unroll
    for (int o = 16; o > 0; o >>= 1) v += __shfl_down_sync(0xffffffffu, v, o);
    if ((t & 31) == 0) ws[t >> 5] = v;
    __syncthreads();
    if (t < 32) {
        int s = ws[t];
        #pragma unroll
        for (int o = 16; o > 0; o >>= 1) s += __shfl_down_sync(0xffffffffu, s, o);
        if (t == 0) g_bsum[b] = s;
    }
}

// scan the 98 block sums (1 block of 128)
__global__ void bscan_k() {
    __shared__ int ws[4];
    int t = threadIdx.x, lane = t & 31, w = t >> 5;
    int v = (t < NBLK) ? g_bsum[t] : 0;
    int x = v;
    #pragma unroll
    for (int o = 1; o < 32; o <<= 1) {
        int y = __shfl_up_sync(0xffffffffu, x, o);
        if (lane >= o) x += y;
    }
    if (lane == 31) ws[w] = x;
    __syncthreads();
    int pre = 0;
    if (w > 0) {
        #pragma unroll
        for (int j = 0; j < 3; j++) if (j < w) pre += ws[j];
    }
    if (t < NBLK) g_boff[t] = pre + x - v;   // exclusive
}

// per-tile rescan + add block offset; write off/cur
__global__ void scatter_scan_k() {
    __shared__ int wsum[32];
    int t = threadIdx.x, b = blockIdx.x;
    int lane = t & 31, w = t >> 5;
    int i = b * 1024 + t;
    int v = (i < NN) ? g_deg[i] : 0;
    int x = v;
    #pragma unroll
    for (int o = 1; o < 32; o <<= 1) {
        int y = __shfl_up_sync(0xffffffffu, x, o);
        if (lane >= o) x += y;
    }
    if (lane == 31) wsum[w] = x;
    __syncthreads();
    if (w == 0) {
        int s = wsum[lane];
        #pragma unroll
        for (int o = 1; o < 32; o <<= 1) {
            int y = __shfl_up_sync(0xffffffffu, s, o);
            if (lane >= o) s += y;
        }
        wsum[lane] = s;
    }
    __syncthreads();
    int pre = (w > 0) ? wsum[w - 1] : 0;
    if (i < NN) {
        int excl = g_boff[b] + pre + x - v;
        g_off[i] = excl;
        g_cur[i] = excl;
    }
}

__global__ void fill_k(const int* __restrict__ ei) {
    int e = blockIdx.x * blockDim.x + threadIdx.x;
    if (e < NE) {
        int src = ei[e];
        int dst = ei[NE + e];
        if ((unsigned)dst < (unsigned)NN && (unsigned)src < (unsigned)NN) {
            int p = atomicAdd(&g_cur[dst], 1);
            if ((unsigned)p < (unsigned)NE) g_srcs[p] = src;
        }
    }
}

// ---------------- weight transpose + tf32 hi/lo split (once, tiny) ----------------
__global__ void wtrans_k(const float* __restrict__ Wl0, const float* __restrict__ Wr0,
                         const float* __restrict__ Wl1, const float* __restrict__ Wr1,
                         const float* __restrict__ Wl2, const float* __restrict__ Wr2) {
    int l = blockIdx.x;  // 0..2
    const float* Wl = (l == 0) ? Wl0 : (l == 1) ? Wl1 : Wl2;
    const float* Wr = (l == 0) ? Wr0 : (l == 1) ? Wr1 : Wr2;
    for (int idx = threadIdx.x; idx < C * C; idx += blockDim.x) {
        int k = idx >> 6, c = idx & 63;
        float vl = Wl[c * C + k];
        float vr = Wr[c * C + k];
        uint32_t hl = f2tf(vl);
        uint32_t hr = f2tf(vr);
        float hlf = __uint_as_float(hl);
        float hrf = __uint_as_float(hr);
        g_Whi[l][0][idx] = hlf;
        g_Wlo[l][0][idx] = __uint_as_float(f2tf(vl - hlf));
        g_Whi[l][1][idx] = hrf;
        g_Wlo[l][1][idx] = __uint_as_float(f2tf(vr - hrf));
    }
}

// ---------------- mean aggregation: warp per node, software-pipelined ----------------
// Chunks of 8 edges; next chunk's src indices prefetched while current chunk's
// 8 independent float2 feature loads are in flight. Tail is two batched phases
// (indices then features) instead of a serial per-edge chain.
__global__ void __launch_bounds__(256) agg_k(const float* __restrict__ x, int insel) {
    const float* in = (insel == 0) ? x : (insel == 1) ? g_h1 : g_h2;
    int warp = (blockIdx.x * blockDim.x + threadIdx.x) >> 5;
    int lane = threadIdx.x & 31;
    if (warp >= NN) return;
    int s = g_off[warp];
    int d = g_deg[warp];
    float ax = 0.f, ay = 0.f;
    int i = 0;

    int idx[8];
    bool have = (i + 8 <= d);
    if (have) {
        #pragma unroll
        for (int j = 0; j < 8; j++) idx[j] = g_srcs[s + j];
    }
    while (have) {
        int nxt[8];
        bool nhave = (i + 16 <= d);
        if (nhave) {
            #pragma unroll
            for (int j = 0; j < 8; j++) nxt[j] = g_srcs[s + i + 8 + j];
        }
        float2 t[8];
        #pragma unroll
        for (int j = 0; j < 8; j++)
            t[j] = ((const float2*)(in + (size_t)idx[j] * C))[lane];
        #pragma unroll
        for (int j = 0; j < 8; j++) { ax += t[j].x; ay += t[j].y; }
        i += 8;
        if (nhave) {
            #pragma unroll
            for (int j = 0; j < 8; j++) idx[j] = nxt[j];
        }
        have = nhave;
    }
    // batched tail (0..7 edges): indices first (independent), then features (MLP=rem)
    int rem = d - i;
    if (rem > 0) {
        int idxr[7];
        #pragma unroll
        for (int j = 0; j < 7; j++) if (j < rem) idxr[j] = g_srcs[s + i + j];
        float2 tr[7];
        #pragma unroll
        for (int j = 0; j < 7; j++)
            if (j < rem) tr[j] = ((const float2*)(in + (size_t)idxr[j] * C))[lane];
        #pragma unroll
        for (int j = 0; j < 7; j++)
            if (j < rem) { ax += tr[j].x; ay += tr[j].y; }
    }
    float di = 1.0f / (float)((d > 0) ? d : 1);
    ((float2*)(g_agg + (size_t)warp * C))[lane] = make_float2(ax * di, ay * di);
}

// ---------------- tensor-core transform: 3xTF32 dual GEMM ----------------
// out[v][c] = sum_k agg[v][k]*WlT[k][c] + bl[c] + sum_k h[v][k]*WrT[k][c] (+relu)
// Block = 64 nodes x 64 channels, 256 threads (8 warps).
#define WS 72
#define AS 68
__global__ void __launch_bounds__(256) xform_k(const float* __restrict__ x,
                                               const float* __restrict__ bl,
                                               float* __restrict__ outp,
                                               int layer, int insel, int outsel,
                                               int relu) {
    extern __shared__ float sm[];
    float* sWlHi = sm;                       // [64][WS]
    float* sWlLo = sWlHi + C * WS;
    float* sWrHi = sWlLo + C * WS;
    float* sWrLo = sWrHi + C * WS;
    float* sA    = sWrLo + C * WS;           // [64][AS]
    float* sH    = sA + 64 * AS;

    const float* hin = (insel == 0) ? x : (insel == 1) ? g_h1 : g_h2;
    float* outb = (outsel == 1) ? g_h1 : (outsel == 2) ? g_h2 : outp;

    int tid = threadIdx.x;
    int v0  = blockIdx.x * 64;

    // stage weights (coalesced reads; STS bank = 8k + c, conflict-free)
    const float* whl = g_Whi[layer][0];
    const float* wll = g_Wlo[layer][0];
    const float* whr = g_Whi[layer][1];
    const float* wlr = g_Wlo[layer][1];
    #pragma unroll
    for (int it = 0; it < 16; it++) {
        int i = it * 256 + tid;
        int k = i >> 6, c = i & 63;
        int p = k * WS + c;
        sWlHi[p] = whl[i];
        sWlLo[p] = wll[i];
        sWrHi[p] = whr[i];
        sWrLo[p] = wlr[i];
    }
    // stage A/H (64 rows x 16 float4)
    #pragma unroll
    for (int it = 0; it < 4; it++) {
        int i = it * 256 + tid;        // 0..1023
        int n = i >> 4, q = i & 15;
        int v = v0 + n;
        float4 a = make_float4(0.f, 0.f, 0.f, 0.f), h = a;
        if (v < NN) {
            a = ((const float4*)(g_agg + (size_t)v * C))[q];
            h = ((const float4*)(hin   + (size_t)v * C))[q];
        }
        int base = n * AS + q * 4;
        sA[base + 0] = a.x; sA[base + 1] = a.y; sA[base + 2] = a.z; sA[base + 3] = a.w;
        sH[base + 0] = h.x; sH[base + 1] = h.y; sH[base + 2] = h.z; sH[base + 3] = h.w;
    }
    __syncthreads();

    int lane = tid & 31, gid = lane >> 2, tig = lane & 3;
    int wid = tid >> 5, mg = wid >> 2, ng = wid & 3;

    // accumulators init with bias
    float acc[2][2][4];
    #pragma unroll
    for (int nt = 0; nt < 2; nt++) {
        int col = ng * 16 + nt * 8 + 2 * tig;
        float b0 = bl[col], b1 = bl[col + 1];
        #pragma unroll
        for (int mt = 0; mt < 2; mt++) {
            acc[mt][nt][0] = b0; acc[mt][nt][1] = b1;
            acc[mt][nt][2] = b0; acc[mt][nt][3] = b1;
        }
    }

    for (int ks = 0; ks < 8; ks++) {
        int k0 = ks * 8;
        uint32_t blh[2][2], bll[2][2], brh[2][2], brl[2][2];
        #pragma unroll
        for (int nt = 0; nt < 2; nt++) {
            int n = ng * 16 + nt * 8 + gid;
            int p0 = (k0 + tig) * WS + n;
            int p1 = (k0 + tig + 4) * WS + n;
            blh[nt][0] = __float_as_uint(sWlHi[p0]); blh[nt][1] = __float_as_uint(sWlHi[p1]);
            bll[nt][0] = __float_as_uint(sWlLo[p0]); bll[nt][1] = __float_as_uint(sWlLo[p1]);
            brh[nt][0] = __float_as_uint(sWrHi[p0]); brh[nt][1] = __float_as_uint(sWrHi[p1]);
            brl[nt][0] = __float_as_uint(sWrLo[p0]); brl[nt][1] = __float_as_uint(sWrLo[p1]);
        }
        #pragma unroll
        for (int mt = 0; mt < 2; mt++) {
            int r = mg * 32 + mt * 16 + gid;   // local row
            int pa = r * AS + k0 + tig;
            int pb = (r + 8) * AS + k0 + tig;
            float a0f = sA[pa], a1f = sA[pb], a2f = sA[pa + 4], a3f = sA[pb + 4];
            float h0f = sH[pa], h1f = sH[pb], h2f = sH[pa + 4], h3f = sH[pb + 4];
            uint32_t ah0 = f2tf(a0f), ah1 = f2tf(a1f), ah2 = f2tf(a2f), ah3 = f2tf(a3f);
            uint32_t al0 = f2tf(a0f - __uint_as_float(ah0));
            uint32_t al1 = f2tf(a1f - __uint_as_float(ah1));
            uint32_t al2 = f2tf(a2f - __uint_as_float(ah2));
            uint32_t al3 = f2tf(a3f - __uint_as_float(ah3));
            uint32_t hh0 = f2tf(h0f), hh1 = f2tf(h1f), hh2 = f2tf(h2f), hh3 = f2tf(h3f);
            uint32_t hl0 = f2tf(h0f - __uint_as_float(hh0));
            uint32_t hl1 = f2tf(h1f - __uint_as_float(hh1));
            uint32_t hl2 = f2tf(h2f - __uint_as_float(hh2));
            uint32_t hl3 = f2tf(h3f - __uint_as_float(hh3));
            #pragma unroll
            for (int nt = 0; nt < 2; nt++) {
                float* cc = acc[mt][nt];
                mma8(cc, ah0, ah1, ah2, ah3, blh[nt][0], blh[nt][1]);  // hi*hi
                mma8(cc, al0, al1, al2, al3, blh[nt][0], blh[nt][1]);  // lo*hi
                mma8(cc, ah0, ah1, ah2, ah3, bll[nt][0], bll[nt][1]);  // hi*lo
                mma8(cc, hh0, hh1, hh2, hh3, brh[nt][0], brh[nt][1]);
                mma8(cc, hl0, hl1, hl2, hl3, brh[nt][0], brh[nt][1]);
                mma8(cc, hh0, hh1, hh2, hh3, brl[nt][0], brl[nt][1]);
            }
        }
    }

    #pragma unroll
    for (int mt = 0; mt < 2; mt++) {
        int row = v0 + mg * 32 + mt * 16 + gid;
        #pragma unroll
        for (int nt = 0; nt < 2; nt++) {
            int col = ng * 16 + nt * 8 + 2 * tig;
            float2 r0 = make_float2(acc[mt][nt][0], acc[mt][nt][1]);
            float2 r1 = make_float2(acc[mt][nt][2], acc[mt][nt][3]);
            if (relu) {
                r0.x = fmaxf(r0.x, 0.f); r0.y = fmaxf(r0.y, 0.f);
                r1.x = fmaxf(r1.x, 0.f); r1.y = fmaxf(r1.y, 0.f);
            }
            if (row < NN)     *(float2*)(outb + (size_t)row * C + col)       = r0;
            if (row + 8 < NN) *(float2*)(outb + (size_t)(row + 8) * C + col) = r1;
        }
    }
}

extern "C" void kernel_launch(void* const* d_in, const int* in_sizes, int n_in,
                              void* d_out, int out_size) {
    const float* x   = (const float*)d_in[0];
    const int*   ei  = (const int*)d_in[1];    // int32 (JAX x64-disabled)
    const float* Wl0 = (const float*)d_in[2];
    const float* bl0 = (const float*)d_in[3];
    const float* Wr0 = (const float*)d_in[4];
    const float* Wl1 = (const float*)d_in[5];
    const float* bl1 = (const float*)d_in[6];
    const float* Wr1 = (const float*)d_in[7];
    const float* Wl2 = (const float*)d_in[8];
    const float* bl2 = (const float*)d_in[9];
    const float* Wr2 = (const float*)d_in[10];
    float* out = (float*)d_out;

    const int XSMEM = (4 * C * WS + 2 * 64 * AS) * (int)sizeof(float);  // 108544 B
    cudaFuncSetAttribute(xform_k, cudaFuncAttributeMaxDynamicSharedMemorySize, XSMEM);

    // CSR build + weight prep
    zero_deg_k<<<(NN + 255) / 256, 256>>>();
    count_k<<<(NE + 255) / 256, 256>>>(ei);
    bsum_k<<<NBLK, 1024>>>();
    bscan_k<<<1, 128>>>();
    scatter_scan_k<<<NBLK, 1024>>>();
    fill_k<<<(NE + 255) / 256, 256>>>(ei);
    wtrans_k<<<3, 256>>>(Wl0, Wr0, Wl1, Wr1, Wl2, Wr2);

    const int AGG_BLOCKS = (NN + 7) / 8;     // 8 warps (nodes) per 256-thread block
    const int XF_BLOCKS  = (NN + 63) / 64;   // 64 nodes per block

    agg_k<<<AGG_BLOCKS, 256>>>(x, 0);
    xform_k<<<XF_BLOCKS, 256, XSMEM>>>(x, bl0, out, 0, 0, 1, 1);  // x    -> g_h1 (relu)
    agg_k<<<AGG_BLOCKS, 256>>>(x, 1);
    xform_k<<<XF_BLOCKS, 256, XSMEM>>>(x, bl1, out, 1, 1, 2, 1);  // g_h1 -> g_h2 (relu)
    agg_k<<<AGG_BLOCKS, 256>>>(x, 2);
    xform_k<<<XF_BLOCKS, 256, XSMEM>>>(x, bl2, out, 2, 2, 0, 0);  // g_h2 -> out
}

// round 10
// speedup vs baseline: 1.2728x; 1.2243x over previous
#include <cuda_runtime.h>
#include <cstdint>

#define NN 100000
#define NE 1600000
#define C  64
#define NBLK 98           // ceil(100000/1024)

// ---- device scratch (no allocation allowed) ----
__device__ int      g_deg[NN];
__device__ int      g_off[NN];
__device__ int      g_cur[NN];
__device__ int      g_srcs[NE];
__device__ float    g_h1[(size_t)NN * C];
__device__ float    g_h2[(size_t)NN * C];
__device__ float    g_agg[(size_t)NN * C];
// packed bf16 weight words [layer][0=WlHi,1=WlLo,2=WrHi,3=WrLo][kk*64+c], kk = k/2
__device__ uint32_t g_W32[3][4][32 * C];
__device__ int      g_bsum[128];
__device__ int      g_boff[128];

// ---------------- helpers ----------------
// pack two floats as bf16x2: low half = a (even k), high half = b (odd k)
__device__ __forceinline__ uint32_t pack_bf16(float a, float b) {
    uint32_t r;
    asm("cvt.rn.bf16x2.f32 %0, %1, %2;" : "=r"(r) : "f"(b), "f"(a));
    return r;
}
__device__ __forceinline__ float bf_lo(uint32_t p) { return __uint_as_float(p << 16); }
__device__ __forceinline__ float bf_hi(uint32_t p) { return __uint_as_float(p & 0xffff0000u); }

__device__ __forceinline__ void mma16(float* c, uint32_t a0, uint32_t a1, uint32_t a2, uint32_t a3,
                                      uint32_t b0, uint32_t b1) {
    asm volatile("mma.sync.aligned.m16n8k16.row.col.f32.bf16.bf16.f32 "
                 "{%0,%1,%2,%3}, {%4,%5,%6,%7}, {%8,%9}, {%0,%1,%2,%3};"
                 : "+f"(c[0]), "+f"(c[1]), "+f"(c[2]), "+f"(c[3])
                 : "r"(a0), "r"(a1), "r"(a2), "r"(a3), "r"(b0), "r"(b1));
}

// ---------------- CSR build ----------------
__global__ void zero_deg_k() {
    int i = blockIdx.x * blockDim.x + threadIdx.x;
    if (i < NN) g_deg[i] = 0;
}

// edge_index is int32 on device (JAX default x64-disabled downcasts int64).
__global__ void count_k(const int* __restrict__ ei) {
    int e = blockIdx.x * blockDim.x + threadIdx.x;
    if (e < NE) {
        int dst = ei[NE + e];
        if ((unsigned)dst < (unsigned)NN) atomicAdd(&g_deg[dst], 1);
    }
}

// two-level scan: block sums
__global__ void bsum_k() {
    __shared__ int ws[32];
    int t = threadIdx.x, b = blockIdx.x;
    int i = b * 1024 + t;
    int v = (i < NN) ? g_deg[i] : 0;
    #pragma unroll
    for (int o = 16; o > 0; o >>= 1) v += __shfl_down_sync(0xffffffffu, v, o);
    if ((t & 31) == 0) ws[t >> 5] = v;
    __syncthreads();
    if (t < 32) {
        int s = ws[t];
        #pragma unroll
        for (int o = 16; o > 0; o >>= 1) s += __shfl_down_sync(0xffffffffu, s, o);
        if (t == 0) g_bsum[b] = s;
    }
}

// scan the 98 block sums (1 block of 128)
__global__ void bscan_k() {
    __shared__ int ws[4];
    int t = threadIdx.x, lane = t & 31, w = t >> 5;
    int v = (t < NBLK) ? g_bsum[t] : 0;
    int x = v;
    #pragma unroll
    for (int o = 1; o < 32; o <<= 1) {
        int y = __shfl_up_sync(0xffffffffu, x, o);
        if (lane >= o) x += y;
    }
    if (lane == 31) ws[w] = x;
    __syncthreads();
    int pre = 0;
    if (w > 0) {
        #pragma unroll
        for (int j = 0; j < 3; j++) if (j < w) pre += ws[j];
    }
    if (t < NBLK) g_boff[t] = pre + x - v;   // exclusive
}

// per-tile rescan + add block offset; write off/cur
__global__ void scatter_scan_k() {
    __shared__ int wsum[32];
    int t = threadIdx.x, b = blockIdx.x;
    int lane = t & 31, w = t >> 5;
    int i = b * 1024 + t;
    int v = (i < NN) ? g_deg[i] : 0;
    int x = v;
    #pragma unroll
    for (int o = 1; o < 32; o <<= 1) {
        int y = __shfl_up_sync(0xffffffffu, x, o);
        if (lane >= o) x += y;
    }
    if (lane == 31) wsum[w] = x;
    __syncthreads();
    if (w == 0) {
        int s = wsum[lane];
        #pragma unroll
        for (int o = 1; o < 32; o <<= 1) {
            int y = __shfl_up_sync(0xffffffffu, s, o);
            if (lane >= o) s += y;
        }
        wsum[lane] = s;
    }
    __syncthreads();
    int pre = (w > 0) ? wsum[w - 1] : 0;
    if (i < NN) {
        int excl = g_boff[b] + pre + x - v;
        g_off[i] = excl;
        g_cur[i] = excl;
    }
}

__global__ void fill_k(const int* __restrict__ ei) {
    int e = blockIdx.x * blockDim.x + threadIdx.x;
    if (e < NE) {
        int src = ei[e];
        int dst = ei[NE + e];
        if ((unsigned)dst < (unsigned)NN && (unsigned)src < (unsigned)NN) {
            int p = atomicAdd(&g_cur[dst], 1);
            if ((unsigned)p < (unsigned)NE) g_srcs[p] = src;
        }
    }
}

// ---------------- weight pack: bf16 hi/lo, transposed k-major (once, tiny) ----------------
__global__ void wtrans_k(const float* __restrict__ Wl0, const float* __restrict__ Wr0,
                         const float* __restrict__ Wl1, const float* __restrict__ Wr1,
                         const float* __restrict__ Wl2, const float* __restrict__ Wr2) {
    int l = blockIdx.x;  // 0..2
    const float* Wl = (l == 0) ? Wl0 : (l == 1) ? Wl1 : Wl2;
    const float* Wr = (l == 0) ? Wr0 : (l == 1) ? Wr1 : Wr2;
    for (int idx = threadIdx.x; idx < 32 * C; idx += blockDim.x) {
        int kk = idx >> 6, c = idx & 63;
        int k0 = 2 * kk, k1 = 2 * kk + 1;
        float vl0 = Wl[c * C + k0], vl1 = Wl[c * C + k1];
        float vr0 = Wr[c * C + k0], vr1 = Wr[c * C + k1];
        uint32_t lh = pack_bf16(vl0, vl1);
        uint32_t rh = pack_bf16(vr0, vr1);
        uint32_t ll = pack_bf16(vl0 - bf_lo(lh), vl1 - bf_hi(lh));
        uint32_t rl = pack_bf16(vr0 - bf_lo(rh), vr1 - bf_hi(rh));
        g_W32[l][0][idx] = lh;
        g_W32[l][1][idx] = ll;
        g_W32[l][2][idx] = rh;
        g_W32[l][3][idx] = rl;
    }
}

// ---------------- mean aggregation: warp per node, software-pipelined (r8) ----------------
__global__ void __launch_bounds__(256) agg_k(const float* __restrict__ x, int insel) {
    const float* in = (insel == 0) ? x : (insel == 1) ? g_h1 : g_h2;
    int warp = (blockIdx.x * blockDim.x + threadIdx.x) >> 5;
    int lane = threadIdx.x & 31;
    if (warp >= NN) return;
    int s = g_off[warp];
    int d = g_deg[warp];
    float ax = 0.f, ay = 0.f;
    int i = 0;

    int idx[8];
    bool have = (i + 8 <= d);
    if (have) {
        #pragma unroll
        for (int j = 0; j < 8; j++) idx[j] = g_srcs[s + j];
    }
    while (have) {
        int nxt[8];
        bool nhave = (i + 16 <= d);
        if (nhave) {
            #pragma unroll
            for (int j = 0; j < 8; j++) nxt[j] = g_srcs[s + i + 8 + j];
        }
        float2 t[8];
        #pragma unroll
        for (int j = 0; j < 8; j++)
            t[j] = ((const float2*)(in + (size_t)idx[j] * C))[lane];
        #pragma unroll
        for (int j = 0; j < 8; j++) { ax += t[j].x; ay += t[j].y; }
        i += 8;
        if (nhave) {
            #pragma unroll
            for (int j = 0; j < 8; j++) idx[j] = nxt[j];
        }
        have = nhave;
    }
    int rem = d - i;
    if (rem > 0) {
        int idxr[7];
        #pragma unroll
        for (int j = 0; j < 7; j++) if (j < rem) idxr[j] = g_srcs[s + i + j];
        float2 tr[7];
        #pragma unroll
        for (int j = 0; j < 7; j++)
            if (j < rem) tr[j] = ((const float2*)(in + (size_t)idxr[j] * C))[lane];
        #pragma unroll
        for (int j = 0; j < 7; j++)
            if (j < rem) { ax += tr[j].x; ay += tr[j].y; }
    }
    float di = 1.0f / (float)((d > 0) ? d : 1);
    ((float2*)(g_agg + (size_t)warp * C))[lane] = make_float2(ax * di, ay * di);
}

// ---------------- tensor-core transform: bf16-split dual GEMM (m16n8k16) ----------------
// out[v][c] = sum_k agg[v][k]*Wl[c][k] + bl[c] + sum_k h[v][k]*Wr[c][k] (+relu)
// x = hi + lo (both bf16). D = hi*hi + lo*hi + hi*lo (lo*lo ~ 2^-16, dropped).
// Block = 64 nodes x 64 channels, 256 threads (8 warps), 4 k-steps of k16.
// Strides: A/H word stride 36 -> LDS bank = (4*gid + tig)%32, bijective;
//          W word stride 72 (row = 64 c-entries + pad) -> LDS bank = (8*tig + gid)%32, bijective.
#define WTS 72   // weight word stride (>= 64 entries per kk row!)
#define ATS 36   // A/H word stride (32 entries per node row)
__global__ void __launch_bounds__(256) xform_k(const float* __restrict__ x,
                                               const float* __restrict__ bl,
                                               float* __restrict__ outp,
                                               int layer, int insel, int outsel,
                                               int relu) {
    extern __shared__ uint32_t sm32[];
    uint32_t* sWlHi = sm32;                    // [32][WTS]
    uint32_t* sWlLo = sWlHi + 32 * WTS;
    uint32_t* sWrHi = sWlLo + 32 * WTS;
    uint32_t* sWrLo = sWrHi + 32 * WTS;
    uint32_t* sAhi  = sWrLo + 32 * WTS;        // [64][ATS]
    uint32_t* sAlo  = sAhi + 64 * ATS;
    uint32_t* sHhi  = sAlo + 64 * ATS;
    uint32_t* sHlo  = sHhi + 64 * ATS;

    const float* hin = (insel == 0) ? x : (insel == 1) ? g_h1 : g_h2;
    float* outb = (outsel == 1) ? g_h1 : (outsel == 2) ? g_h2 : outp;

    int tid = threadIdx.x;
    int v0  = blockIdx.x * 64;

    // stage packed weights (coalesced reads; STS bank = (8kk + c)%32, conflict-free)
    const uint32_t* wlh = g_W32[layer][0];
    const uint32_t* wll = g_W32[layer][1];
    const uint32_t* wrh = g_W32[layer][2];
    const uint32_t* wrl = g_W32[layer][3];
    #pragma unroll
    for (int it = 0; it < 8; it++) {
        int i = it * 256 + tid;            // 0..2047
        int kk = i >> 6, c = i & 63;
        int p = kk * WTS + c;
        sWlHi[p] = wlh[i];
        sWlLo[p] = wll[i];
        sWrHi[p] = wrh[i];
        sWrLo[p] = wrl[i];
    }
    // stage A/H: hi/lo bf16 packed words (64 rows x 16 float4 each)
    #pragma unroll
    for (int it = 0; it < 4; it++) {
        int i = it * 256 + tid;            // 0..1023
        int n = i >> 4, q = i & 15;        // q: float4 index -> words 2q, 2q+1
        int v = v0 + n;
        float4 a = make_float4(0.f, 0.f, 0.f, 0.f), h = a;
        if (v < NN) {
            a = ((const float4*)(g_agg + (size_t)v * C))[q];
            h = ((const float4*)(hin   + (size_t)v * C))[q];
        }
        int base = n * ATS + 2 * q;
        uint32_t ah0 = pack_bf16(a.x, a.y);
        uint32_t ah1 = pack_bf16(a.z, a.w);
        sAhi[base + 0] = ah0;
        sAhi[base + 1] = ah1;
        sAlo[base + 0] = pack_bf16(a.x - bf_lo(ah0), a.y - bf_hi(ah0));
        sAlo[base + 1] = pack_bf16(a.z - bf_lo(ah1), a.w - bf_hi(ah1));
        uint32_t hh0 = pack_bf16(h.x, h.y);
        uint32_t hh1 = pack_bf16(h.z, h.w);
        sHhi[base + 0] = hh0;
        sHhi[base + 1] = hh1;
        sHlo[base + 0] = pack_bf16(h.x - bf_lo(hh0), h.y - bf_hi(hh0));
        sHlo[base + 1] = pack_bf16(h.z - bf_lo(hh1), h.w - bf_hi(hh1));
    }
    __syncthreads();

    int lane = tid & 31, gid = lane >> 2, tig = lane & 3;
    int wid = tid >> 5, mg = wid >> 2, ng = wid & 3;

    // accumulators init with bias
    float acc[2][2][4];
    #pragma unroll
    for (int nt = 0; nt < 2; nt++) {
        int col = ng * 16 + nt * 8 + 2 * tig;
        float b0 = bl[col], b1 = bl[col + 1];
        #pragma unroll
        for (int mt = 0; mt < 2; mt++) {
            acc[mt][nt][0] = b0; acc[mt][nt][1] = b1;
            acc[mt][nt][2] = b0; acc[mt][nt][3] = b1;
        }
    }

    #pragma unroll
    for (int ks = 0; ks < 4; ks++) {
        int kk0 = ks * 8;
        // B fragments: b0 = word(kk0+tig, n), b1 = word(kk0+tig+4, n)
        uint32_t blh[2][2], bll[2][2], brh[2][2], brl[2][2];
        #pragma unroll
        for (int nt = 0; nt < 2; nt++) {
            int n = ng * 16 + nt * 8 + gid;
            int p0 = (kk0 + tig) * WTS + n;
            int p1 = (kk0 + tig + 4) * WTS + n;
            blh[nt][0] = sWlHi[p0]; blh[nt][1] = sWlHi[p1];
            bll[nt][0] = sWlLo[p0]; bll[nt][1] = sWlLo[p1];
            brh[nt][0] = sWrHi[p0]; brh[nt][1] = sWrHi[p1];
            brl[nt][0] = sWrLo[p0]; brl[nt][1] = sWrLo[p1];
        }
        #pragma unroll
        for (int mt = 0; mt < 2; mt++) {
            int r = mg * 32 + mt * 16 + gid;   // local row
            int pa = r * ATS + kk0 + tig;
            int pb = (r + 8) * ATS + kk0 + tig;
            // A frags: a0=(r, klo), a1=(r+8, klo), a2=(r, khi), a3=(r+8, khi)
            uint32_t ah0 = sAhi[pa], ah1 = sAhi[pb], ah2 = sAhi[pa + 4], ah3 = sAhi[pb + 4];
            uint32_t al0 = sAlo[pa], al1 = sAlo[pb], al2 = sAlo[pa + 4], al3 = sAlo[pb + 4];
            uint32_t hh0 = sHhi[pa], hh1 = sHhi[pb], hh2 = sHhi[pa + 4], hh3 = sHhi[pb + 4];
            uint32_t hl0 = sHlo[pa], hl1 = sHlo[pb], hl2 = sHlo[pa + 4], hl3 = sHlo[pb + 4];
            #pragma unroll
            for (int nt = 0; nt < 2; nt++) {
                float* cc = acc[mt][nt];
                mma16(cc, ah0, ah1, ah2, ah3, blh[nt][0], blh[nt][1]);  // hi*hi
                mma16(cc, al0, al1, al2, al3, blh[nt][0], blh[nt][1]);  // lo*hi
                mma16(cc, ah0, ah1, ah2, ah3, bll[nt][0], bll[nt][1]);  // hi*lo
                mma16(cc, hh0, hh1, hh2, hh3, brh[nt][0], brh[nt][1]);
                mma16(cc, hl0, hl1, hl2, hl3, brh[nt][0], brh[nt][1]);
                mma16(cc, hh0, hh1, hh2, hh3, brl[nt][0], brl[nt][1]);
            }
        }
    }

    #pragma unroll
    for (int mt = 0; mt < 2; mt++) {
        int row = v0 + mg * 32 + mt * 16 + gid;
        #pragma unroll
        for (int nt = 0; nt < 2; nt++) {
            int col = ng * 16 + nt * 8 + 2 * tig;
            float2 r0 = make_float2(acc[mt][nt][0], acc[mt][nt][1]);
            float2 r1 = make_float2(acc[mt][nt][2], acc[mt][nt][3]);
            if (relu) {
                r0.x = fmaxf(r0.x, 0.f); r0.y = fmaxf(r0.y, 0.f);
                r1.x = fmaxf(r1.x, 0.f); r1.y = fmaxf(r1.y, 0.f);
            }
            if (row < NN)     *(float2*)(outb + (size_t)row * C + col)       = r0;
            if (row + 8 < NN) *(float2*)(outb + (size_t)(row + 8) * C + col) = r1;
        }
    }
}

extern "C" void kernel_launch(void* const* d_in, const int* in_sizes, int n_in,
                              void* d_out, int out_size) {
    const float* x   = (const float*)d_in[0];
    const int*   ei  = (const int*)d_in[1];    // int32 (JAX x64-disabled)
    const float* Wl0 = (const float*)d_in[2];
    const float* bl0 = (const float*)d_in[3];
    const float* Wr0 = (const float*)d_in[4];
    const float* Wl1 = (const float*)d_in[5];
    const float* bl1 = (const float*)d_in[6];
    const float* Wr1 = (const float*)d_in[7];
    const float* Wl2 = (const float*)d_in[8];
    const float* bl2 = (const float*)d_in[9];
    const float* Wr2 = (const float*)d_in[10];
    float* out = (float*)d_out;

    const int XSMEM = (4 * 32 * WTS + 4 * 64 * ATS) * (int)sizeof(uint32_t);  // 73728 B
    cudaFuncSetAttribute(xform_k, cudaFuncAttributeMaxDynamicSharedMemorySize, XSMEM);

    // CSR build + weight prep
    zero_deg_k<<<(NN + 255) / 256, 256>>>();
    count_k<<<(NE + 255) / 256, 256>>>(ei);
    bsum_k<<<NBLK, 1024>>>();
    bscan_k<<<1, 128>>>();
    scatter_scan_k<<<NBLK, 1024>>>();
    fill_k<<<(NE + 255) / 256, 256>>>(ei);
    wtrans_k<<<3, 256>>>(Wl0, Wr0, Wl1, Wr1, Wl2, Wr2);

    const int AGG_BLOCKS = (NN + 7) / 8;     // 8 warps (nodes) per 256-thread block
    const int XF_BLOCKS  = (NN + 63) / 64;   // 64 nodes per block

    agg_k<<<AGG_BLOCKS, 256>>>(x, 0);
    xform_k<<<XF_BLOCKS, 256, XSMEM>>>(x, bl0, out, 0, 0, 1, 1);  // x    -> g_h1 (relu)
    agg_k<<<AGG_BLOCKS, 256>>>(x, 1);
    xform_k<<<XF_BLOCKS, 256, XSMEM>>>(x, bl1, out, 1, 1, 2, 1);  // g_h1 -> g_h2 (relu)
    agg_k<<<AGG_BLOCKS, 256>>>(x, 2);
    xform_k<<<XF_BLOCKS, 256, XSMEM>>>(x, bl2, out, 2, 2, 0, 0);  // g_h2 -> out
}